// round 8
// baseline (speedup 1.0000x reference)
#include <cuda_runtime.h>
#include <cstdint>

#define BB 16
#define LL0 1024
#define LL1 3136
#define CC 768
#define HH 8
#define LOG2E 1.4426950408889634f

typedef unsigned long long u64;

__device__ __forceinline__ u64 pack2(float lo, float hi) {
    u64 r; asm("mov.b64 %0, {%1,%2};" : "=l"(r) : "f"(lo), "f"(hi)); return r;
}
__device__ __forceinline__ void unpack2(u64 v, float& lo, float& hi) {
    asm("mov.b64 {%0,%1}, %2;" : "=f"(lo), "=f"(hi) : "l"(v));
}
__device__ __forceinline__ u64 fma2(u64 a, u64 b, u64 c) {
    u64 d; asm("fma.rn.f32x2 %0,%1,%2,%3;" : "=l"(d) : "l"(a), "l"(b), "l"(c)); return d;
}
__device__ __forceinline__ u64 mul2(u64 a, u64 b) {
    u64 d; asm("mul.rn.f32x2 %0,%1,%2;" : "=l"(d) : "l"(a), "l"(b)); return d;
}
__device__ __forceinline__ u64 add2(u64 a, u64 b) {
    u64 d; asm("add.rn.f32x2 %0,%1,%2;" : "=l"(d) : "l"(a), "l"(b)); return d;
}
__device__ __forceinline__ float ex2f(float x) {
    float r; asm("ex2.approx.f32 %0, %1;" : "=f"(r) : "f"(x)); return r;
}
__device__ __forceinline__ float rcpf(float x) {
    float r; asm("rcp.approx.f32 %0, %1;" : "=f"(r) : "f"(x)); return r;
}

// ---------------- scratch ----------------
__device__ float g_x0t[BB * LL0 * HH];
__device__ float g_x1t[BB * LL1 * HH];
__device__ float g_num0[8][BB * LL0 * HH];   // row-softmax numerator partials (m split 8)
__device__ float g_den0[8][BB * LL0];
__device__ float g_num1[4][BB * LL1 * HH];   // col-softmax numerator partials (l split 4)
__device__ float g_den1[4][BB * LL1];
__device__ float g_x10[BB * LL1 * HH];
__device__ float g_S0[BB * HH];              // zero at module load; re-zeroed at end of k_out
__device__ float g_S1p[BB * 13 * 8];         // per-(b,chunk) fovea partials for x1_0
__device__ float g_x0o[BB * LL0 * HH];

// ---------------- K1: input projections (+ fused S0 exp-sum atomics) ----------------
// W staged in smem as 4 u64 planes with additive swizzle: (k,p) -> slot p*960 + k + (k>>2).
__global__ void __launch_bounds__(256) k_proj(const float* __restrict__ x,
                       const float* __restrict__ W00, const float* __restrict__ b00,
                       const float* __restrict__ W01, const float* __restrict__ b01) {
    __shared__ __align__(16) u64 sWT[4 * 960];  // 30.7KB
    const int tid = threadIdx.x;

    const int i_start = (blockIdx.x * 32) % (LL0 + LL1);
    const bool is0 = (i_start < LL0);
    const float* Wg = is0 ? W00 : W01;
    for (int i = tid; i < CC * 4; i += 256) {
        const int k = i >> 2, p = i & 3;
        const u64 v = *(const u64*)(Wg + k * HH + 2 * p);
        sWT[p * 960 + k + (k >> 2)] = v;
    }
    __syncthreads();

    const int warp = blockIdx.x * 8 + (tid >> 5);
    const int lane = tid & 31;
    const int r0 = warp * 4;
    const int LT = LL0 + LL1;
    const int b = r0 / LT;
    const int i = r0 % LT;
    const float* xp = x + (size_t)r0 * CC;
    const int lb = lane * 5;

    u64 acc[4][4];
#pragma unroll
    for (int r = 0; r < 4; r++)
#pragma unroll
        for (int p = 0; p < 4; p++) acc[r][p] = 0ull;

#pragma unroll
    for (int it = 0; it < 6; it++) {
        const int k = it * 128 + lane * 4;
        float4 xv[4];
#pragma unroll
        for (int r = 0; r < 4; r++) xv[r] = __ldcs((const float4*)(xp + (size_t)r * CC + k));
#pragma unroll
        for (int j = 0; j < 4; j++) {
            const int ws = it * 160 + lb + j;
            const u64 w0 = sWT[ws];
            const u64 w1 = sWT[960 + ws];
            const u64 w2 = sWT[1920 + ws];
            const u64 w3 = sWT[2880 + ws];
#pragma unroll
            for (int r = 0; r < 4; r++) {
                const float xs = (j == 0) ? xv[r].x : (j == 1) ? xv[r].y : (j == 2) ? xv[r].z : xv[r].w;
                const u64 xx = pack2(xs, xs);
                acc[r][0] = fma2(xx, w0, acc[r][0]);
                acc[r][1] = fma2(xx, w1, acc[r][1]);
                acc[r][2] = fma2(xx, w2, acc[r][2]);
                acc[r][3] = fma2(xx, w3, acc[r][3]);
            }
        }
    }
#pragma unroll
    for (int off = 16; off; off >>= 1)
#pragma unroll
        for (int r = 0; r < 4; r++)
#pragma unroll
            for (int p = 0; p < 4; p++)
                acc[r][p] = add2(acc[r][p], __shfl_xor_sync(0xffffffffu, acc[r][p], off));

    if (lane == 0) {
        const float* bias = is0 ? b00 : b01;
        float bv[8];
#pragma unroll
        for (int d = 0; d < 8; d++) bv[d] = bias[d];
        float* dst = is0 ? (g_x0t + ((size_t)b * LL0 + i) * HH)
                         : (g_x1t + ((size_t)b * LL1 + (i - LL0)) * HH);
        float se[8] = {0, 0, 0, 0, 0, 0, 0, 0};
#pragma unroll
        for (int r = 0; r < 4; r++) {
            float o[8];
#pragma unroll
            for (int p = 0; p < 4; p++) unpack2(acc[r][p], o[2 * p], o[2 * p + 1]);
#pragma unroll
            for (int d = 0; d < 8; d++) o[d] += bv[d];
            *(float4*)(dst + (size_t)r * HH) = make_float4(o[0], o[1], o[2], o[3]);
            *(float4*)(dst + (size_t)r * HH + 4) = make_float4(o[4], o[5], o[6], o[7]);
            if (is0) {
#pragma unroll
                for (int d = 0; d < 8; d++) se[d] += ex2f(o[d] * LOG2E);
            }
        }
        if (is0) {
#pragma unroll
            for (int d = 0; d < 8; d++) atomicAdd(&g_S0[b * 8 + d], se[d]);
        }
    }
}

// ---------------- merged attention: blocks [0,512) = row dir, [512,1344) = col dir ----------------
__global__ void __launch_bounds__(256, 4) k_attn() {
    __shared__ __align__(16) u64 sT[196][8];  // 12.25KB, col part uses first 128 rows
    const int tid = threadIdx.x;
    const int blk = blockIdx.x;

    if (blk < 512) {
        // -------- row direction --------
        const int lc = blk & 3, ms = (blk >> 2) & 7, b = blk >> 5;
        const float* src = g_x1t + ((size_t)b * LL1 + ms * 392) * HH;
        for (int m = tid; m < 392; m += 256) {
            const float4 v0 = *(const float4*)(src + m * 8);
            const float4 v1 = *(const float4*)(src + m * 8 + 4);
            float* f = (float*)&sT[m >> 1][0] + (m & 1);
            f[0] = v0.x; f[2] = v0.y; f[4] = v0.z; f[6] = v0.w;
            f[8] = v1.x; f[10] = v1.y; f[12] = v1.z; f[14] = v1.w;
        }
        __syncthreads();

        const int l = lc * 256 + tid;
        const float* a = g_x0t + ((size_t)b * LL0 + l) * HH;
        u64 av[8];
#pragma unroll
        for (int d = 0; d < 8; d++) { const float s = a[d] * LOG2E; av[d] = pack2(s, s); }

        u64 acc[8] = {0, 0, 0, 0, 0, 0, 0, 0};
        u64 den2 = 0ull;
#pragma unroll 4
        for (int i = 0; i < 196; i++) {
            const ulonglong2* q = (const ulonglong2*)&sT[i][0];
            const ulonglong2 qa = q[0], qb = q[1], qc = q[2], qd = q[3];
            u64 s0 = mul2(av[0], qa.x);
            u64 s1 = mul2(av[1], qa.y);
            s0 = fma2(av[2], qb.x, s0);
            s1 = fma2(av[3], qb.y, s1);
            s0 = fma2(av[4], qc.x, s0);
            s1 = fma2(av[5], qc.y, s1);
            s0 = fma2(av[6], qd.x, s0);
            s1 = fma2(av[7], qd.y, s1);
            s0 = add2(s0, s1);
            float Slo, Shi;
            unpack2(s0, Slo, Shi);
            const u64 ee = pack2(ex2f(Slo), ex2f(Shi));
            acc[0] = fma2(ee, qa.x, acc[0]);
            acc[1] = fma2(ee, qa.y, acc[1]);
            acc[2] = fma2(ee, qb.x, acc[2]);
            acc[3] = fma2(ee, qb.y, acc[3]);
            acc[4] = fma2(ee, qc.x, acc[4]);
            acc[5] = fma2(ee, qc.y, acc[5]);
            acc[6] = fma2(ee, qd.x, acc[6]);
            acc[7] = fma2(ee, qd.y, acc[7]);
            den2 = add2(den2, ee);
        }
        float o[8];
#pragma unroll
        for (int d = 0; d < 8; d++) { float lo, hi; unpack2(acc[d], lo, hi); o[d] = lo + hi; }
        float dl, dh;
        unpack2(den2, dl, dh);
        float* nd = g_num0[ms] + ((size_t)b * LL0 + l) * HH;
        *(float4*)(nd) = make_float4(o[0], o[1], o[2], o[3]);
        *(float4*)(nd + 4) = make_float4(o[4], o[5], o[6], o[7]);
        g_den0[ms][b * LL0 + l] = dl + dh;
    } else {
        // -------- col direction --------
        const int cb = blk - 512;
        const int mc = cb % 13;
        const int t2 = cb / 13;
        const int ls = t2 & 3, b = t2 >> 2;
        const float* src = g_x0t + ((size_t)b * LL0 + ls * 256) * HH;
        if (tid < 256) {
            const int m = tid;
            const float4 v0 = *(const float4*)(src + m * 8);
            const float4 v1 = *(const float4*)(src + m * 8 + 4);
            float* f = (float*)&sT[m >> 1][0] + (m & 1);
            f[0] = v0.x; f[2] = v0.y; f[4] = v0.z; f[6] = v0.w;
            f[8] = v1.x; f[10] = v1.y; f[12] = v1.z; f[14] = v1.w;
        }
        __syncthreads();

        const int m = mc * 256 + tid;
        const bool act = (m < LL1);
        const int mm = act ? m : (LL1 - 1);
        const float* a = g_x1t + ((size_t)b * LL1 + mm) * HH;
        u64 av[8];
#pragma unroll
        for (int d = 0; d < 8; d++) { const float s = a[d] * LOG2E; av[d] = pack2(s, s); }

        u64 acc[8] = {0, 0, 0, 0, 0, 0, 0, 0};
        u64 den2 = 0ull;
#pragma unroll 4
        for (int i = 0; i < 128; i++) {
            const ulonglong2* q = (const ulonglong2*)&sT[i][0];
            const ulonglong2 qa = q[0], qb = q[1], qc = q[2], qd = q[3];
            u64 s0 = mul2(av[0], qa.x);
            u64 s1 = mul2(av[1], qa.y);
            s0 = fma2(av[2], qb.x, s0);
            s1 = fma2(av[3], qb.y, s1);
            s0 = fma2(av[4], qc.x, s0);
            s1 = fma2(av[5], qc.y, s1);
            s0 = fma2(av[6], qd.x, s0);
            s1 = fma2(av[7], qd.y, s1);
            s0 = add2(s0, s1);
            float Slo, Shi;
            unpack2(s0, Slo, Shi);
            const u64 ee = pack2(ex2f(Slo), ex2f(Shi));
            acc[0] = fma2(ee, qa.x, acc[0]);
            acc[1] = fma2(ee, qa.y, acc[1]);
            acc[2] = fma2(ee, qb.x, acc[2]);
            acc[3] = fma2(ee, qb.y, acc[3]);
            acc[4] = fma2(ee, qc.x, acc[4]);
            acc[5] = fma2(ee, qc.y, acc[5]);
            acc[6] = fma2(ee, qd.x, acc[6]);
            acc[7] = fma2(ee, qd.y, acc[7]);
            den2 = add2(den2, ee);
        }
        if (act) {
            float o[8];
#pragma unroll
            for (int d = 0; d < 8; d++) { float lo, hi; unpack2(acc[d], lo, hi); o[d] = lo + hi; }
            float dl, dh;
            unpack2(den2, dl, dh);
            float* nd = g_num1[ls] + ((size_t)b * LL1 + m) * HH;
            *(float4*)(nd) = make_float4(o[0], o[1], o[2], o[3]);
            *(float4*)(nd + 4) = make_float4(o[4], o[5], o[6], o[7]);
            g_den1[ls][b * LL1 + m] = dl + dh;
        }
    }
}

// ---------------- merged mid: blocks [0,64) = combine0, [64,272) = reduce1 ----------------
__global__ void k_mid() {
    const int blk = blockIdx.x;
    const int tid = threadIdx.x;
    if (blk < 64) {
        // combine0: x0o = fovea(x0t) + x0_1
        const int b = blk >> 2;
        const int l = (blk & 3) * 256 + tid;
        const size_t base = ((size_t)b * LL0 + l) * HH;
        float num[8] = {0, 0, 0, 0, 0, 0, 0, 0};
        float den = 0.f;
#pragma unroll
        for (int s = 0; s < 8; s++) {
            den += g_den0[s][b * LL0 + l];
            const float4* p = (const float4*)(g_num0[s] + base);
            const float4 v0 = p[0], v1 = p[1];
            num[0] += v0.x; num[1] += v0.y; num[2] += v0.z; num[3] += v0.w;
            num[4] += v1.x; num[5] += v1.y; num[6] += v1.z; num[7] += v1.w;
        }
        const float inv = rcpf(den);
        const float* xt = g_x0t + base;
        const float* S = g_S0 + b * 8;
        float o[8];
#pragma unroll
        for (int d = 0; d < 8; d++) {
            const float t = xt[d];
            o[d] = ex2f(t * LOG2E) * rcpf(S[d]) * t + num[d] * inv;
        }
        float* dst = g_x0o + base;
        *(float4*)(dst) = make_float4(o[0], o[1], o[2], o[3]);
        *(float4*)(dst + 4) = make_float4(o[4], o[5], o[6], o[7]);
    } else {
        // reduce1: x1_0 = sum(num1)/sum(den1) + S1 chunk partial (no atomics)
        __shared__ float sred[8][256];
        const int cb = blk - 64;
        const int b = cb / 13;
        const int mchunk = cb % 13;
        const int m = mchunk * 256 + tid;
        const bool act = (m < LL1);
        float o[8] = {0, 0, 0, 0, 0, 0, 0, 0};
        if (act) {
            const size_t base = ((size_t)b * LL1 + m) * HH;
            float num[8] = {0, 0, 0, 0, 0, 0, 0, 0};
            float den = 0.f;
#pragma unroll
            for (int s = 0; s < 4; s++) {
                den += g_den1[s][b * LL1 + m];
                const float4* p = (const float4*)(g_num1[s] + base);
                const float4 v0 = p[0], v1 = p[1];
                num[0] += v0.x; num[1] += v0.y; num[2] += v0.z; num[3] += v0.w;
                num[4] += v1.x; num[5] += v1.y; num[6] += v1.z; num[7] += v1.w;
            }
            const float inv = rcpf(den);
#pragma unroll
            for (int d = 0; d < 8; d++) o[d] = num[d] * inv;
            float* dst = g_x10 + base;
            *(float4*)(dst) = make_float4(o[0], o[1], o[2], o[3]);
            *(float4*)(dst + 4) = make_float4(o[4], o[5], o[6], o[7]);
        }
#pragma unroll
        for (int d = 0; d < 8; d++) sred[d][tid] = act ? ex2f(o[d] * LOG2E) : 0.f;
        __syncthreads();
        for (int off = 128; off; off >>= 1) {
            if (tid < off)
#pragma unroll
                for (int d = 0; d < 8; d++) sred[d][tid] += sred[d][tid + off];
            __syncthreads();
        }
        if (tid < 8) g_S1p[(b * 13 + mchunk) * 8 + tid] = sred[tid][0];
    }
}

// ---------------- merged output projections (+ fused combine1 in part1) ----------------
// blocks [0,1024) = out0, [1024,4224) = out1. Block = (b, l-chunk of 128, c-chunk of 96).
__global__ void __launch_bounds__(256) k_out(const float* __restrict__ W1, const float* __restrict__ b1,
                                             const float* __restrict__ W2, const float* __restrict__ b2,
                                             float* __restrict__ out) {
    __shared__ __align__(16) float sW[96 * 8];
    __shared__ float sB[96];
    __shared__ float sInv1[8];
    const int blk = blockIdx.x;
    const int tid = threadIdx.x;
    const int w = tid >> 5, lane = tid & 31;

    const bool part0 = (blk < 1024);
    int ccb, lcb, b;
    const float* Wsrc;
    const float* Bsrc;
    if (part0) {
        ccb = blk & 7; lcb = (blk >> 3) & 7; b = blk >> 6;
        Wsrc = W1; Bsrc = b1;
    } else {
        const int cb = blk - 1024;
        ccb = cb & 7;
        const int t2 = cb >> 3;
        lcb = t2 % 25; b = t2 / 25;
        Wsrc = W2; Bsrc = b2;
    }
    const int c0 = ccb * 96;
    for (int t = tid; t < 768; t += 256) {
        const int k = t / 96, ci = t % 96;
        sW[ci * 8 + k] = Wsrc[k * CC + c0 + ci];
    }
    if (tid < 96) sB[tid] = Bsrc[c0 + tid];
    if (!part0 && tid >= 96 && tid < 104) {
        const int d = tid - 96;
        float s = 0.f;
#pragma unroll
        for (int j = 0; j < 13; j++) s += g_S1p[(b * 13 + j) * 8 + d];
        sInv1[d] = rcpf(s);
    }
    __syncthreads();

    const int l0 = lcb * 128 + lane * 4;
    const bool active = part0 || (l0 < LL1);
    const int LD = part0 ? LL0 : LL1;
    float* obase = part0 ? (out + (size_t)b * CC * LL0)
                         : (out + (size_t)BB * CC * LL0 + (size_t)b * CC * LL1);
    u64 xr[4][4];
    if (part0) {
        const u64* xo = (const u64*)(g_x0o + ((size_t)b * LL0 + l0) * HH);
#pragma unroll
        for (int r = 0; r < 4; r++) {
            const ulonglong2 v0 = *(const ulonglong2*)(xo + r * 4);
            const ulonglong2 v1 = *(const ulonglong2*)(xo + r * 4 + 2);
            xr[r][0] = v0.x; xr[r][1] = v0.y; xr[r][2] = v1.x; xr[r][3] = v1.y;
        }
    } else if (active) {
        // fused combine1: x1o = fovea(x1_0) + x1t, computed on the fly
        const float* x10p = g_x10 + ((size_t)b * LL1 + l0) * HH;
        const float* x1tp = g_x1t + ((size_t)b * LL1 + l0) * HH;
#pragma unroll
        for (int r = 0; r < 4; r++) {
            const float4 a0 = *(const float4*)(x10p + r * 8);
            const float4 a1 = *(const float4*)(x10p + r * 8 + 4);
            const float4 t0 = *(const float4*)(x1tp + r * 8);
            const float4 t1 = *(const float4*)(x1tp + r * 8 + 4);
            float o[8];
            o[0] = ex2f(a0.x * LOG2E) * sInv1[0] * a0.x + t0.x;
            o[1] = ex2f(a0.y * LOG2E) * sInv1[1] * a0.y + t0.y;
            o[2] = ex2f(a0.z * LOG2E) * sInv1[2] * a0.z + t0.z;
            o[3] = ex2f(a0.w * LOG2E) * sInv1[3] * a0.w + t0.w;
            o[4] = ex2f(a1.x * LOG2E) * sInv1[4] * a1.x + t1.x;
            o[5] = ex2f(a1.y * LOG2E) * sInv1[5] * a1.y + t1.y;
            o[6] = ex2f(a1.z * LOG2E) * sInv1[6] * a1.z + t1.z;
            o[7] = ex2f(a1.w * LOG2E) * sInv1[7] * a1.w + t1.w;
            xr[r][0] = pack2(o[0], o[1]);
            xr[r][1] = pack2(o[2], o[3]);
            xr[r][2] = pack2(o[4], o[5]);
            xr[r][3] = pack2(o[6], o[7]);
        }
    }
#pragma unroll 2
    for (int j = 0; j < 12; j++) {
        const int ci = w * 12 + j;
        const u64* wq = (const u64*)(sW + ci * 8);
        const u64 w0 = wq[0], w1 = wq[1], w2 = wq[2], w3 = wq[3];
        const float bias = sB[ci];
        if (active) {
            float o[4];
#pragma unroll
            for (int r = 0; r < 4; r++) {
                u64 a0 = mul2(xr[r][0], w0);
                u64 a1 = mul2(xr[r][1], w1);
                a0 = fma2(xr[r][2], w2, a0);
                a1 = fma2(xr[r][3], w3, a1);
                a0 = add2(a0, a1);
                float lo, hi;
                unpack2(a0, lo, hi);
                o[r] = bias + lo + hi;
            }
            __stcs((float4*)(obase + (size_t)(c0 + ci) * LD + l0), make_float4(o[0], o[1], o[2], o[3]));
        }
    }
    // re-zero the S0 atomic accumulator for the next graph replay
    // (safe: S0 is only read by k_mid, which precedes this kernel)
    if (blk == 0 && tid < BB * HH) g_S0[tid] = 0.f;
}

extern "C" void kernel_launch(void* const* d_in, const int* in_sizes, int n_in,
                              void* d_out, int out_size) {
    const float* x   = (const float*)d_in[0];
    const float* W00 = (const float*)d_in[1];
    const float* b00 = (const float*)d_in[2];
    const float* W01 = (const float*)d_in[3];
    const float* b01 = (const float*)d_in[4];
    const float* W1  = (const float*)d_in[5];
    const float* b1  = (const float*)d_in[6];
    const float* W2  = (const float*)d_in[7];
    const float* b2  = (const float*)d_in[8];
    float* out = (float*)d_out;

    k_proj<<<2080, 256>>>(x, W00, b00, W01, b01);
    k_attn<<<1344, 256>>>();
    k_mid<<<272, 256>>>();
    k_out<<<4224, 256>>>(W1, b1, W2, b2, out);
}

// round 9
// speedup vs baseline: 1.9364x; 1.9364x over previous
#include <cuda_runtime.h>
#include <cstdint>

#define BB 16
#define LL0 1024
#define LL1 3136
#define CC 768
#define HH 8
#define LOG2E 1.4426950408889634f

typedef unsigned long long u64;

__device__ __forceinline__ u64 pack2(float lo, float hi) {
    u64 r; asm("mov.b64 %0, {%1,%2};" : "=l"(r) : "f"(lo), "f"(hi)); return r;
}
__device__ __forceinline__ void unpack2(u64 v, float& lo, float& hi) {
    asm("mov.b64 {%0,%1}, %2;" : "=f"(lo), "=f"(hi) : "l"(v));
}
__device__ __forceinline__ u64 fma2(u64 a, u64 b, u64 c) {
    u64 d; asm("fma.rn.f32x2 %0,%1,%2,%3;" : "=l"(d) : "l"(a), "l"(b), "l"(c)); return d;
}
__device__ __forceinline__ u64 mul2(u64 a, u64 b) {
    u64 d; asm("mul.rn.f32x2 %0,%1,%2;" : "=l"(d) : "l"(a), "l"(b)); return d;
}
__device__ __forceinline__ u64 add2(u64 a, u64 b) {
    u64 d; asm("add.rn.f32x2 %0,%1,%2;" : "=l"(d) : "l"(a), "l"(b)); return d;
}
__device__ __forceinline__ float ex2f(float x) {
    float r; asm("ex2.approx.f32 %0, %1;" : "=f"(r) : "f"(x)); return r;
}
__device__ __forceinline__ float rcpf(float x) {
    float r; asm("rcp.approx.f32 %0, %1;" : "=f"(r) : "f"(x)); return r;
}

// ---------------- scratch ----------------
__device__ float g_x0t[BB * LL0 * HH];
__device__ float g_x1t[BB * LL1 * HH];
__device__ float g_num0[8][BB * LL0 * HH];   // row-softmax numerator partials (m split 8)
__device__ float g_den0[8][BB * LL0];
__device__ float g_num1[4][BB * LL1 * HH];   // col-softmax numerator partials (l split 4)
__device__ float g_den1[4][BB * LL1];
__device__ float g_x10[BB * LL1 * HH];
__device__ float g_S0[BB * HH];              // zero at module load; re-zeroed at end of k_out
__device__ float g_S1[BB * HH];
__device__ float g_x0o[BB * LL0 * HH];
__device__ float g_x1o[BB * LL1 * HH];

// ---------------- K1: input projections (+ fused S0 exp-sum atomics) ----------------
// W staged in smem as 4 u64 planes with additive swizzle: (k,p) -> slot p*960 + k + (k>>2).
__global__ void __launch_bounds__(256) k_proj(const float* __restrict__ x,
                       const float* __restrict__ W00, const float* __restrict__ b00,
                       const float* __restrict__ W01, const float* __restrict__ b01) {
    __shared__ __align__(16) u64 sWT[4 * 960];  // 30.7KB
    const int tid = threadIdx.x;

    const int i_start = (blockIdx.x * 32) % (LL0 + LL1);
    const bool is0 = (i_start < LL0);
    const float* Wg = is0 ? W00 : W01;
    for (int i = tid; i < CC * 4; i += 256) {
        const int k = i >> 2, p = i & 3;
        const u64 v = *(const u64*)(Wg + k * HH + 2 * p);
        sWT[p * 960 + k + (k >> 2)] = v;
    }
    __syncthreads();

    const int warp = blockIdx.x * 8 + (tid >> 5);
    const int lane = tid & 31;
    const int r0 = warp * 4;
    const int LT = LL0 + LL1;
    const int b = r0 / LT;
    const int i = r0 % LT;
    const float* xp = x + (size_t)r0 * CC;
    const int lb = lane * 5;

    u64 acc[4][4];
#pragma unroll
    for (int r = 0; r < 4; r++)
#pragma unroll
        for (int p = 0; p < 4; p++) acc[r][p] = 0ull;

#pragma unroll
    for (int it = 0; it < 6; it++) {
        const int k = it * 128 + lane * 4;
        float4 xv[4];
#pragma unroll
        for (int r = 0; r < 4; r++) xv[r] = __ldcs((const float4*)(xp + (size_t)r * CC + k));
#pragma unroll
        for (int j = 0; j < 4; j++) {
            const int ws = it * 160 + lb + j;
            const u64 w0 = sWT[ws];
            const u64 w1 = sWT[960 + ws];
            const u64 w2 = sWT[1920 + ws];
            const u64 w3 = sWT[2880 + ws];
#pragma unroll
            for (int r = 0; r < 4; r++) {
                const float xs = (j == 0) ? xv[r].x : (j == 1) ? xv[r].y : (j == 2) ? xv[r].z : xv[r].w;
                const u64 xx = pack2(xs, xs);
                acc[r][0] = fma2(xx, w0, acc[r][0]);
                acc[r][1] = fma2(xx, w1, acc[r][1]);
                acc[r][2] = fma2(xx, w2, acc[r][2]);
                acc[r][3] = fma2(xx, w3, acc[r][3]);
            }
        }
    }
#pragma unroll
    for (int off = 16; off; off >>= 1)
#pragma unroll
        for (int r = 0; r < 4; r++)
#pragma unroll
            for (int p = 0; p < 4; p++)
                acc[r][p] = add2(acc[r][p], __shfl_xor_sync(0xffffffffu, acc[r][p], off));

    if (lane == 0) {
        const float* bias = is0 ? b00 : b01;
        float bv[8];
#pragma unroll
        for (int d = 0; d < 8; d++) bv[d] = bias[d];
        float* dst = is0 ? (g_x0t + ((size_t)b * LL0 + i) * HH)
                         : (g_x1t + ((size_t)b * LL1 + (i - LL0)) * HH);
        float se[8] = {0, 0, 0, 0, 0, 0, 0, 0};
#pragma unroll
        for (int r = 0; r < 4; r++) {
            float o[8];
#pragma unroll
            for (int p = 0; p < 4; p++) unpack2(acc[r][p], o[2 * p], o[2 * p + 1]);
#pragma unroll
            for (int d = 0; d < 8; d++) o[d] += bv[d];
            *(float4*)(dst + (size_t)r * HH) = make_float4(o[0], o[1], o[2], o[3]);
            *(float4*)(dst + (size_t)r * HH + 4) = make_float4(o[4], o[5], o[6], o[7]);
            if (is0) {
#pragma unroll
                for (int d = 0; d < 8; d++) se[d] += ex2f(o[d] * LOG2E);
            }
        }
        if (is0) {
#pragma unroll
            for (int d = 0; d < 8; d++) atomicAdd(&g_S0[b * 8 + d], se[d]);
        }
    }
}

// ---------------- merged attention, 128-thread blocks ----------------
// blocks [0,1024) = row dir (lc 8 x ms 8 x b 16), [1024,2624) = col dir (mc 25 x ls 4 x b 16)
__global__ void __launch_bounds__(128) k_attn() {
    __shared__ __align__(16) u64 sT[196][8];  // 12.25KB, col part uses first 128 rows
    const int tid = threadIdx.x;
    const int blk = blockIdx.x;

    if (blk < 1024) {
        // -------- row direction: 128 l's vs 392 m's --------
        const int lc = blk & 7, ms = (blk >> 3) & 7, b = blk >> 6;
        const float* src = g_x1t + ((size_t)b * LL1 + ms * 392) * HH;
        for (int m = tid; m < 392; m += 128) {
            const float4 v0 = *(const float4*)(src + m * 8);
            const float4 v1 = *(const float4*)(src + m * 8 + 4);
            float* f = (float*)&sT[m >> 1][0] + (m & 1);
            f[0] = v0.x; f[2] = v0.y; f[4] = v0.z; f[6] = v0.w;
            f[8] = v1.x; f[10] = v1.y; f[12] = v1.z; f[14] = v1.w;
        }
        __syncthreads();

        const int l = lc * 128 + tid;
        const float* a = g_x0t + ((size_t)b * LL0 + l) * HH;
        u64 av[8];
#pragma unroll
        for (int d = 0; d < 8; d++) { const float s = a[d] * LOG2E; av[d] = pack2(s, s); }

        u64 acc[8] = {0, 0, 0, 0, 0, 0, 0, 0};
        u64 den2 = 0ull;
#pragma unroll 4
        for (int i = 0; i < 196; i++) {
            const ulonglong2* q = (const ulonglong2*)&sT[i][0];
            const ulonglong2 qa = q[0], qb = q[1], qc = q[2], qd = q[3];
            u64 s0 = mul2(av[0], qa.x);
            u64 s1 = mul2(av[1], qa.y);
            s0 = fma2(av[2], qb.x, s0);
            s1 = fma2(av[3], qb.y, s1);
            s0 = fma2(av[4], qc.x, s0);
            s1 = fma2(av[5], qc.y, s1);
            s0 = fma2(av[6], qd.x, s0);
            s1 = fma2(av[7], qd.y, s1);
            s0 = add2(s0, s1);
            float Slo, Shi;
            unpack2(s0, Slo, Shi);
            const u64 ee = pack2(ex2f(Slo), ex2f(Shi));
            acc[0] = fma2(ee, qa.x, acc[0]);
            acc[1] = fma2(ee, qa.y, acc[1]);
            acc[2] = fma2(ee, qb.x, acc[2]);
            acc[3] = fma2(ee, qb.y, acc[3]);
            acc[4] = fma2(ee, qc.x, acc[4]);
            acc[5] = fma2(ee, qc.y, acc[5]);
            acc[6] = fma2(ee, qd.x, acc[6]);
            acc[7] = fma2(ee, qd.y, acc[7]);
            den2 = add2(den2, ee);
        }
        float o[8];
#pragma unroll
        for (int d = 0; d < 8; d++) { float lo, hi; unpack2(acc[d], lo, hi); o[d] = lo + hi; }
        float dl, dh;
        unpack2(den2, dl, dh);
        float* nd = g_num0[ms] + ((size_t)b * LL0 + l) * HH;
        *(float4*)(nd) = make_float4(o[0], o[1], o[2], o[3]);
        *(float4*)(nd + 4) = make_float4(o[4], o[5], o[6], o[7]);
        g_den0[ms][b * LL0 + l] = dl + dh;
    } else {
        // -------- col direction: 128 m's vs 256 l's --------
        const int cb = blk - 1024;
        const int mc = cb % 25;
        const int t2 = cb / 25;
        const int ls = t2 & 3, b = t2 >> 2;
        const float* src = g_x0t + ((size_t)b * LL0 + ls * 256) * HH;
        for (int m = tid; m < 256; m += 128) {
            const float4 v0 = *(const float4*)(src + m * 8);
            const float4 v1 = *(const float4*)(src + m * 8 + 4);
            float* f = (float*)&sT[m >> 1][0] + (m & 1);
            f[0] = v0.x; f[2] = v0.y; f[4] = v0.z; f[6] = v0.w;
            f[8] = v1.x; f[10] = v1.y; f[12] = v1.z; f[14] = v1.w;
        }
        __syncthreads();

        const int m = mc * 128 + tid;
        const bool act = (m < LL1);
        const int mm = act ? m : (LL1 - 1);
        const float* a = g_x1t + ((size_t)b * LL1 + mm) * HH;
        u64 av[8];
#pragma unroll
        for (int d = 0; d < 8; d++) { const float s = a[d] * LOG2E; av[d] = pack2(s, s); }

        u64 acc[8] = {0, 0, 0, 0, 0, 0, 0, 0};
        u64 den2 = 0ull;
#pragma unroll 4
        for (int i = 0; i < 128; i++) {
            const ulonglong2* q = (const ulonglong2*)&sT[i][0];
            const ulonglong2 qa = q[0], qb = q[1], qc = q[2], qd = q[3];
            u64 s0 = mul2(av[0], qa.x);
            u64 s1 = mul2(av[1], qa.y);
            s0 = fma2(av[2], qb.x, s0);
            s1 = fma2(av[3], qb.y, s1);
            s0 = fma2(av[4], qc.x, s0);
            s1 = fma2(av[5], qc.y, s1);
            s0 = fma2(av[6], qd.x, s0);
            s1 = fma2(av[7], qd.y, s1);
            s0 = add2(s0, s1);
            float Slo, Shi;
            unpack2(s0, Slo, Shi);
            const u64 ee = pack2(ex2f(Slo), ex2f(Shi));
            acc[0] = fma2(ee, qa.x, acc[0]);
            acc[1] = fma2(ee, qa.y, acc[1]);
            acc[2] = fma2(ee, qb.x, acc[2]);
            acc[3] = fma2(ee, qb.y, acc[3]);
            acc[4] = fma2(ee, qc.x, acc[4]);
            acc[5] = fma2(ee, qc.y, acc[5]);
            acc[6] = fma2(ee, qd.x, acc[6]);
            acc[7] = fma2(ee, qd.y, acc[7]);
            den2 = add2(den2, ee);
        }
        if (act) {
            float o[8];
#pragma unroll
            for (int d = 0; d < 8; d++) { float lo, hi; unpack2(acc[d], lo, hi); o[d] = lo + hi; }
            float dl, dh;
            unpack2(den2, dl, dh);
            float* nd = g_num1[ls] + ((size_t)b * LL1 + m) * HH;
            *(float4*)(nd) = make_float4(o[0], o[1], o[2], o[3]);
            *(float4*)(nd + 4) = make_float4(o[4], o[5], o[6], o[7]);
            g_den1[ls][b * LL1 + m] = dl + dh;
        }
    }
}

// ---------------- merged mid: blocks [0,64) = combine0, [64,272) = reduce1 ----------------
__global__ void k_mid() {
    const int blk = blockIdx.x;
    const int tid = threadIdx.x;
    if (blk < 64) {
        // combine0: x0o = fovea(x0t) + x0_1
        const int b = blk >> 2;
        const int l = (blk & 3) * 256 + tid;
        const size_t base = ((size_t)b * LL0 + l) * HH;
        float num[8] = {0, 0, 0, 0, 0, 0, 0, 0};
        float den = 0.f;
#pragma unroll
        for (int s = 0; s < 8; s++) {
            den += g_den0[s][b * LL0 + l];
            const float4* p = (const float4*)(g_num0[s] + base);
            const float4 v0 = p[0], v1 = p[1];
            num[0] += v0.x; num[1] += v0.y; num[2] += v0.z; num[3] += v0.w;
            num[4] += v1.x; num[5] += v1.y; num[6] += v1.z; num[7] += v1.w;
        }
        const float inv = rcpf(den);
        const float* xt = g_x0t + base;
        const float* S = g_S0 + b * 8;
        float o[8];
#pragma unroll
        for (int d = 0; d < 8; d++) {
            const float t = xt[d];
            o[d] = ex2f(t * LOG2E) * rcpf(S[d]) * t + num[d] * inv;
        }
        float* dst = g_x0o + base;
        *(float4*)(dst) = make_float4(o[0], o[1], o[2], o[3]);
        *(float4*)(dst + 4) = make_float4(o[4], o[5], o[6], o[7]);
    } else {
        // reduce1: x1_0 = sum(num1)/sum(den1) + fused S1 reduction
        __shared__ float sred[8][256];
        const int cb = blk - 64;
        const int b = cb / 13;
        const int m = (cb % 13) * 256 + tid;
        const bool act = (m < LL1);
        float o[8] = {0, 0, 0, 0, 0, 0, 0, 0};
        if (act) {
            const size_t base = ((size_t)b * LL1 + m) * HH;
            float num[8] = {0, 0, 0, 0, 0, 0, 0, 0};
            float den = 0.f;
#pragma unroll
            for (int s = 0; s < 4; s++) {
                den += g_den1[s][b * LL1 + m];
                const float4* p = (const float4*)(g_num1[s] + base);
                const float4 v0 = p[0], v1 = p[1];
                num[0] += v0.x; num[1] += v0.y; num[2] += v0.z; num[3] += v0.w;
                num[4] += v1.x; num[5] += v1.y; num[6] += v1.z; num[7] += v1.w;
            }
            const float inv = rcpf(den);
#pragma unroll
            for (int d = 0; d < 8; d++) o[d] = num[d] * inv;
            float* dst = g_x10 + base;
            *(float4*)(dst) = make_float4(o[0], o[1], o[2], o[3]);
            *(float4*)(dst + 4) = make_float4(o[4], o[5], o[6], o[7]);
        }
#pragma unroll
        for (int d = 0; d < 8; d++) sred[d][tid] = act ? ex2f(o[d] * LOG2E) : 0.f;
        __syncthreads();
        for (int off = 128; off; off >>= 1) {
            if (tid < off)
#pragma unroll
                for (int d = 0; d < 8; d++) sred[d][tid] += sred[d][tid + off];
            __syncthreads();
        }
        if (tid < 8) atomicAdd(&g_S1[b * 8 + tid], sred[tid][0]);
    }
}

// ---------------- combine1: x1o = fovea(x1_0) + x1t ----------------
__global__ void k_combine1() {  // grid (13, 16), block 256
    const int b = blockIdx.y;
    const int m = blockIdx.x * 256 + threadIdx.x;
    if (m >= LL1) return;
    const size_t base = ((size_t)b * LL1 + m) * HH;
    const float* xt = g_x1t + base;
    const float* x10 = g_x10 + base;
    const float* S = g_S1 + b * 8;
    float o[8];
#pragma unroll
    for (int d = 0; d < 8; d++) {
        const float t = x10[d];
        o[d] = ex2f(t * LOG2E) * rcpf(S[d]) * t + xt[d];
    }
    float* dst = g_x1o + base;
    *(float4*)(dst) = make_float4(o[0], o[1], o[2], o[3]);
    *(float4*)(dst + 4) = make_float4(o[4], o[5], o[6], o[7]);
}

// ---------------- merged output projections (W slice + x rows staged in smem) ----------------
// blocks [0,1024) = out0, [1024,4224) = out1. Block = (b, l-chunk of 128, c-chunk of 96).
__global__ void __launch_bounds__(256) k_out(const float* __restrict__ W1, const float* __restrict__ b1,
                                             const float* __restrict__ W2, const float* __restrict__ b2,
                                             float* __restrict__ out) {
    __shared__ __align__(16) float sW[96 * 8];
    __shared__ float sB[96];
    __shared__ __align__(16) u64 sX[544];  // 128 rows x 4 u64, skew slot(i)=i+(i>>4)
    const int blk = blockIdx.x;
    const int tid = threadIdx.x;
    const int w = tid >> 5, lane = tid & 31;

    const bool part0 = (blk < 1024);
    int ccb, lcb, b;
    const float* Wsrc;
    const float* Bsrc;
    if (part0) {
        ccb = blk & 7; lcb = (blk >> 3) & 7; b = blk >> 6;
        Wsrc = W1; Bsrc = b1;
    } else {
        const int cb = blk - 1024;
        ccb = cb & 7;
        const int t2 = cb >> 3;
        lcb = t2 % 25; b = t2 / 25;
        Wsrc = W2; Bsrc = b2;
    }
    const int c0 = ccb * 96;
    for (int t = tid; t < 768; t += 256) {
        const int k = t / 96, ci = t % 96;
        sW[ci * 8 + k] = Wsrc[k * CC + c0 + ci];
    }
    if (tid < 96) sB[tid] = Bsrc[c0 + tid];

    // stage x rows coalesced: u64 i -> smem slot i + (i>>4)
    const int row0 = lcb * 128;
    const int nrows = part0 ? 128 : ((LL1 - row0 < 128) ? (LL1 - row0) : 128);
    const u64* gx = part0 ? (const u64*)(g_x0o + ((size_t)b * LL0 + row0) * HH)
                          : (const u64*)(g_x1o + ((size_t)b * LL1 + row0) * HH);
    for (int i = tid; i < nrows * 4; i += 256) sX[i + (i >> 4)] = gx[i];
    __syncthreads();

    const int l0 = row0 + lane * 4;
    const bool active = part0 || (l0 < LL1);
    const int LD = part0 ? LL0 : LL1;
    float* obase = part0 ? (out + (size_t)b * CC * LL0)
                         : (out + (size_t)BB * CC * LL0 + (size_t)b * CC * LL1);
    u64 xr[4][4];
    if (active) {
        const int sb = 17 * lane;
#pragma unroll
        for (int r = 0; r < 4; r++)
#pragma unroll
            for (int p = 0; p < 4; p++) xr[r][p] = sX[sb + 4 * r + p];
    }
#pragma unroll 2
    for (int j = 0; j < 12; j++) {
        const int ci = w * 12 + j;
        const u64* wq = (const u64*)(sW + ci * 8);
        const u64 w0 = wq[0], w1 = wq[1], w2 = wq[2], w3 = wq[3];
        const float bias = sB[ci];
        if (active) {
            float o[4];
#pragma unroll
            for (int r = 0; r < 4; r++) {
                u64 a0 = mul2(xr[r][0], w0);
                u64 a1 = mul2(xr[r][1], w1);
                a0 = fma2(xr[r][2], w2, a0);
                a1 = fma2(xr[r][3], w3, a1);
                a0 = add2(a0, a1);
                float lo, hi;
                unpack2(a0, lo, hi);
                o[r] = bias + lo + hi;
            }
            __stcs((float4*)(obase + (size_t)(c0 + ci) * LD + l0), make_float4(o[0], o[1], o[2], o[3]));
        }
    }
    // re-zero the atomic accumulators for the next graph replay
    if (blk == 0) {
        if (tid < BB * HH) g_S0[tid] = 0.f;
        else if (tid < 2 * BB * HH) g_S1[tid - BB * HH] = 0.f;
    }
}

extern "C" void kernel_launch(void* const* d_in, const int* in_sizes, int n_in,
                              void* d_out, int out_size) {
    const float* x   = (const float*)d_in[0];
    const float* W00 = (const float*)d_in[1];
    const float* b00 = (const float*)d_in[2];
    const float* W01 = (const float*)d_in[3];
    const float* b01 = (const float*)d_in[4];
    const float* W1  = (const float*)d_in[5];
    const float* b1  = (const float*)d_in[6];
    const float* W2  = (const float*)d_in[7];
    const float* b2  = (const float*)d_in[8];
    float* out = (float*)d_out;

    k_proj<<<2080, 256>>>(x, W00, b00, W01, b01);
    k_attn<<<2624, 128>>>();
    k_mid<<<272, 256>>>();
    k_combine1<<<dim3(13, 16), 256>>>();
    k_out<<<4224, 256>>>(W1, b1, W2, b2, out);
}